// round 15
// baseline (speedup 1.0000x reference)
#include <cuda_runtime.h>
#include <cuda_fp16.h>
#include <math.h>
#include <stdint.h>

// ---------------- problem constants ----------------
#define BB   4
#define SS   2048
#define DD   1024
#define HH   16
#define DKK  64
#define FFN  4096
#define NTOK (BB*SS)
#define NELT (NTOK*DD)
#define ASZ  ((long long)BB*HH*SS*SS)
#define NROWS (BB*HH*SS)

#define KC    64   // K-chunk in fp16 elements (= 32 words = 128B per row)
#define SPAD  36   // smem row stride in 32-bit words (32 data + 4 pad)

// ---------------- scratch (device globals) ----------------
__device__ __half g_h  [NELT];
__device__ __half g_QKV[NTOK*3*DD];
__device__ __half g_Qg [NELT];
__device__ __half g_VT [NELT];
__device__ __half g_ctx[NELT];
__device__ float  g_x1 [NELT];
__device__ __half g_h2 [NELT];
__device__ float  g_x2 [NELT];
__device__ __half g_t1 [NTOK*2*DD];
__device__ __half g_ff1[NTOK*FFN];
__device__ float  g_cwgt[NTOK];
__device__ float  g_rowsum[NROWS];
__device__ __half g_wqkvT[3*DD*DD];
__device__ __half g_woT [DD*DD];
__device__ __half g_cw1T[DD*2*DD];
__device__ __half g_cw2T[2*DD*DD];
__device__ __half g_fw1T[DD*FFN];
__device__ __half g_fw2T[DD*FFN];
__device__ __half g_e   [(size_t)ASZ];   // unnormalized exp(scores), fp16
__device__ float  g_attn_fb[(size_t)ASZ];// fallback fp32 attn output

// ---------------- helpers ----------------
__device__ __forceinline__ uint32_t smem_u32(const void* p) {
    uint32_t a;
    asm("{ .reg .u64 t; cvta.to.shared.u64 t, %1; cvt.u32.u64 %0, t; }"
        : "=r"(a) : "l"(p));
    return a;
}
__device__ __forceinline__ float geluf(float x) {
    return 0.5f * x * (1.0f + erff(x * 0.70710678118654752f));
}
__device__ __forceinline__ void mma_f16(float* d, const uint32_t* a, const uint32_t* b) {
    asm volatile(
        "mma.sync.aligned.m16n8k16.row.col.f32.f16.f16.f32 "
        "{%0,%1,%2,%3}, {%4,%5,%6,%7}, {%8,%9}, {%0,%1,%2,%3};"
        : "+f"(d[0]), "+f"(d[1]), "+f"(d[2]), "+f"(d[3])
        : "r"(a[0]), "r"(a[1]), "r"(a[2]), "r"(a[3]), "r"(b[0]), "r"(b[1]));
}
__device__ __forceinline__ void cp16(uint32_t dst, const void* src) {
    asm volatile("cp.async.cg.shared.global [%0], [%1], 16;"
                 :: "r"(dst), "l"(src) : "memory");
}
#define CP_COMMIT() asm volatile("cp.async.commit_group;" ::: "memory")
#define CP_WAIT1()  asm volatile("cp.async.wait_group 1;" ::: "memory")

// ---------------- templated fp16 tensor-core GEMM ----------------
// C = A[M,K] @ B[N,K]^T, A/B fp16 (pre-rounded at producers), fp32 accumulate.
// K-chunk 64 elements, 3-stage cp.async pipeline; 8 warps, 256 thr.
// MODE: 1 = acc -> half             2 = gelu(acc+bias) -> half
//       3 = res + acc (+bias) -> float
//       4 = res + beta*h2 + cwgt[m]*(acc+bias) -> float
//       5 = e=h(exp(acc*scale)) -> half, atomic row sums of rounded e
//       6 = h(acc * inv_rowsum[m]) -> half (ctx; ATTN streams fp32 attn)
template<int BM, int BN, int MT, bool ATTN, int MODE>
__global__ void __launch_bounds__(256) tc_gemm(
    const __half* __restrict__ A, const __half* __restrict__ B,
    void* __restrict__ Cv, float* __restrict__ Aout, float* __restrict__ rowsum,
    int M, int K, int lda, int ldb, int ldc,
    int batchH, long long sAb, long long sAh, long long sBb, long long sBh,
    long long sCb, long long sCh,
    float scale, const float* __restrict__ bias, const float* __restrict__ res,
    const __half* __restrict__ h2p, const float* __restrict__ cwgt,
    const float* __restrict__ beta_ptr)
{
    constexpr int WN  = BN / 64;
    constexpr int AI  = BM / 64;
    constexpr int BI  = BN / 64;
    constexpr int STG = (BM + BN) * SPAD;   // 32-bit words per stage
    constexpr bool OUTH = (MODE == 1 || MODE == 2 || MODE == 5 || MODE == 6);

    extern __shared__ uint32_t sm[];
    uint32_t sbase = smem_u32(sm);

    int z = blockIdx.z;
    int zb = z / batchH, zh = z - zb * batchH;
    A += (long long)zb * sAb + (long long)zh * sAh;
    B += (long long)zb * sBb + (long long)zh * sBh;
    float*  Cf = (float*)Cv  + (OUTH ? 0 : ((long long)zb * sCb + (long long)zh * sCh));
    __half* Ch = (__half*)Cv + (OUTH ? ((long long)zb * sCb + (long long)zh * sCh) : 0);

    int tid = threadIdx.x;
    int wid = tid >> 5, lane = tid & 31;
    int wm = wid / WN, wn = wid % WN;
    int g = lane >> 2, t = lane & 3;
    int m0 = blockIdx.y * BM, n0 = blockIdx.x * BN;

    float acc[MT][8][4];
    #pragma unroll
    for (int i = 0; i < MT; i++)
        #pragma unroll
        for (int j = 0; j < 8; j++)
            #pragma unroll
            for (int q = 0; q < 4; q++) acc[i][j][q] = 0.f;

    int lr0 = tid >> 2;
    int lw0 = (tid & 3) * 4;       // word offset in smem row
    int hc0 = (tid & 3) * 8;       // half offset in gmem row
    const __half* Ag = A + (long long)(m0 + lr0) * lda + hc0;
    const __half* Bg = B + (long long)(n0 + lr0) * ldb + hc0;
    int NC = K / KC;

    float invL[AI];
    float* AoutB = nullptr;
    if (ATTN) {
        const float* rs = rowsum + (long long)z * M;
        #pragma unroll
        for (int i = 0; i < AI; i++) invL[i] = 1.f / rs[m0 + lr0 + i * 64];
        AoutB = Aout + (long long)zb * sAb + (long long)zh * sAh;
    }

    auto issue = [&](int c) {
        int s = c % 3;
        uint32_t ab = sbase + (uint32_t)(s * STG) * 4u;
        uint32_t bb = ab + (uint32_t)(BM * SPAD) * 4u;
        const __half* Ap = Ag + c * KC;
        #pragma unroll
        for (int i = 0; i < AI; i++) {
            cp16(ab + (uint32_t)((lr0 + i * 64) * SPAD + lw0) * 4u,
                 Ap + (long long)(i * 64) * lda);
            cp16(ab + (uint32_t)((lr0 + i * 64) * SPAD + lw0 + 16) * 4u,
                 Ap + (long long)(i * 64) * lda + 32);
        }
        const __half* Bp = Bg + c * KC;
        #pragma unroll
        for (int i = 0; i < BI; i++) {
            cp16(bb + (uint32_t)((lr0 + i * 64) * SPAD + lw0) * 4u,
                 Bp + (long long)(i * 64) * ldb);
            cp16(bb + (uint32_t)((lr0 + i * 64) * SPAD + lw0 + 16) * 4u,
                 Bp + (long long)(i * 64) * ldb + 32);
        }
    };

    issue(0); CP_COMMIT();
    if (NC > 1) issue(1);
    CP_COMMIT();

    for (int c = 0; c < NC; c++) {
        int s = c % 3;
        uint32_t* stA = sm + s * STG;
        uint32_t* stB = stA + BM * SPAD;

        CP_WAIT1();
        __syncthreads();

        if (ATTN) {   // stream normalized fp32 attention weights out of smem
            #pragma unroll
            for (int i = 0; i < AI; i++) {
                #pragma unroll
                for (int jj = 0; jj < 2; jj++) {
                    uint4 w = *reinterpret_cast<uint4*>(
                        &stA[(lr0 + i * 64) * SPAD + lw0 + jj * 16]);
                    __half2 p0 = *reinterpret_cast<__half2*>(&w.x);
                    __half2 p1 = *reinterpret_cast<__half2*>(&w.y);
                    __half2 p2 = *reinterpret_cast<__half2*>(&w.z);
                    __half2 p3 = *reinterpret_cast<__half2*>(&w.w);
                    float iv = invL[i];
                    float4 o0 = make_float4(__low2float(p0) * iv, __high2float(p0) * iv,
                                            __low2float(p1) * iv, __high2float(p1) * iv);
                    float4 o1 = make_float4(__low2float(p2) * iv, __high2float(p2) * iv,
                                            __low2float(p3) * iv, __high2float(p3) * iv);
                    float* dst = AoutB + (long long)(m0 + lr0 + i * 64) * lda
                                 + c * KC + hc0 + jj * 32;
                    *reinterpret_cast<float4*>(dst)     = o0;
                    *reinterpret_cast<float4*>(dst + 4) = o1;
                }
            }
        }

        if (c + 2 < NC) issue(c + 2);
        CP_COMMIT();

        #pragma unroll
        for (int ks = 0; ks < 4; ks++) {           // 4 x k16 per 64-chunk
            int kk = ks * 8;                        // word offset
            uint32_t af[MT][4], bf[8][2];
            #pragma unroll
            for (int mt = 0; mt < MT; mt++) {
                int row = wm * (MT * 16) + mt * 16 + g;
                af[mt][0] = stA[row * SPAD + kk + t];
                af[mt][1] = stA[(row + 8) * SPAD + kk + t];
                af[mt][2] = stA[row * SPAD + kk + t + 4];
                af[mt][3] = stA[(row + 8) * SPAD + kk + t + 4];
            }
            #pragma unroll
            for (int nt = 0; nt < 8; nt++) {
                int col = wn * 64 + nt * 8 + g;
                bf[nt][0] = stB[col * SPAD + kk + t];
                bf[nt][1] = stB[col * SPAD + kk + t + 4];
            }
            #pragma unroll
            for (int mt = 0; mt < MT; mt++)
                #pragma unroll
                for (int nt = 0; nt < 8; nt++)
                    mma_f16(acc[mt][nt], af[mt], bf[nt]);
        }
    }

    // ---------------- epilogue ----------------
    float betav = (MODE == 4) ? beta_ptr[0] : 0.f;
    const float* rsE = (MODE == 6) ? rowsum + (long long)z * M : nullptr;
    float* rsA = (MODE == 5) ? rowsum + (long long)z * M : nullptr;

    #pragma unroll
    for (int mt = 0; mt < MT; mt++) {
        int r0 = m0 + wm * (MT * 16) + mt * 16 + g;
        int r1 = r0 + 8;
        float cw0 = 0.f, cw1 = 0.f, inv0 = 0.f, inv1 = 0.f;
        if (MODE == 4) { cw0 = cwgt[r0]; cw1 = cwgt[r1]; }
        if (MODE == 6) { inv0 = 1.f / rsE[r0]; inv1 = 1.f / rsE[r1]; }
        float s0 = 0.f, s1 = 0.f;
        #pragma unroll
        for (int nt = 0; nt < 8; nt++) {
            int n = n0 + wn * 64 + nt * 8 + 2 * t;
            long long co0 = (long long)r0 * ldc + n;
            long long co1 = (long long)r1 * ldc + n;
            float v00 = acc[mt][nt][0], v01 = acc[mt][nt][1];
            float v10 = acc[mt][nt][2], v11 = acc[mt][nt][3];
            if (MODE == 1) {
                *reinterpret_cast<__half2*>(Ch + co0) = __floats2half2_rn(v00, v01);
                *reinterpret_cast<__half2*>(Ch + co1) = __floats2half2_rn(v10, v11);
            } else if (MODE == 2) {
                float b0 = bias[n], b1 = bias[n + 1];
                *reinterpret_cast<__half2*>(Ch + co0) =
                    __floats2half2_rn(geluf(v00 + b0), geluf(v01 + b1));
                *reinterpret_cast<__half2*>(Ch + co1) =
                    __floats2half2_rn(geluf(v10 + b0), geluf(v11 + b1));
            } else if (MODE == 3) {
                float b0 = bias ? bias[n] : 0.f, b1 = bias ? bias[n + 1] : 0.f;
                float2 q0 = *reinterpret_cast<const float2*>(res + co0);
                float2 q1 = *reinterpret_cast<const float2*>(res + co1);
                *reinterpret_cast<float2*>(Cf + co0) =
                    make_float2(q0.x + v00 + b0, q0.y + v01 + b1);
                *reinterpret_cast<float2*>(Cf + co1) =
                    make_float2(q1.x + v10 + b0, q1.y + v11 + b1);
            } else if (MODE == 4) {
                float b0 = bias[n], b1 = bias[n + 1];
                float2 q0 = *reinterpret_cast<const float2*>(res + co0);
                float2 q1 = *reinterpret_cast<const float2*>(res + co1);
                __half2 hh0 = *reinterpret_cast<const __half2*>(h2p + co0);
                __half2 hh1 = *reinterpret_cast<const __half2*>(h2p + co1);
                *reinterpret_cast<float2*>(Cf + co0) = make_float2(
                    q0.x + betav * __low2float(hh0) + cw0 * (v00 + b0),
                    q0.y + betav * __high2float(hh0) + cw0 * (v01 + b1));
                *reinterpret_cast<float2*>(Cf + co1) = make_float2(
                    q1.x + betav * __low2float(hh1) + cw1 * (v10 + b0),
                    q1.y + betav * __high2float(hh1) + cw1 * (v11 + b1));
            } else if (MODE == 5) {
                __half2 e0 = __floats2half2_rn(__expf(v00 * scale), __expf(v01 * scale));
                __half2 e1 = __floats2half2_rn(__expf(v10 * scale), __expf(v11 * scale));
                *reinterpret_cast<__half2*>(Ch + co0) = e0;
                *reinterpret_cast<__half2*>(Ch + co1) = e1;
                s0 += __low2float(e0) + __high2float(e0);
                s1 += __low2float(e1) + __high2float(e1);
            } else { // MODE == 6
                *reinterpret_cast<__half2*>(Ch + co0) =
                    __floats2half2_rn(v00 * inv0, v01 * inv0);
                *reinterpret_cast<__half2*>(Ch + co1) =
                    __floats2half2_rn(v10 * inv1, v11 * inv1);
            }
        }
        if (MODE == 5) {
            s0 += __shfl_xor_sync(0xffffffffu, s0, 1);
            s0 += __shfl_xor_sync(0xffffffffu, s0, 2);
            s1 += __shfl_xor_sync(0xffffffffu, s1, 1);
            s1 += __shfl_xor_sync(0xffffffffu, s1, 2);
            if (t == 0) {
                atomicAdd(rsA + r0, s0);
                atomicAdd(rsA + r1, s1);
            }
        }
    }
}

// ---------------- zero kernel ----------------
__global__ void __launch_bounds__(256) zero_kernel(float* p, int n) {
    int i = blockIdx.x * 256 + threadIdx.x;
    if (i < n) p[i] = 0.f;
}

// ---------------- transpose (templated in/out types; out = fp16) ----------------
template<typename TI>
__global__ void __launch_bounds__(256) transpose_kernel(
    const TI* __restrict__ in, __half* __restrict__ out,
    int R, int C, int ldi, int ldo,
    int batchH, long long sIb, long long sIh, long long sOb, long long sOh)
{
    __shared__ float tile[32][33];
    int z = blockIdx.z;
    int zb = z / batchH, zh = z - zb * batchH;
    in  += (long long)zb * sIb + (long long)zh * sIh;
    out += (long long)zb * sOb + (long long)zh * sOh;
    int r0 = blockIdx.y * 32, c0 = blockIdx.x * 32;
    int tx = threadIdx.x & 31, ty = threadIdx.x >> 5;
    #pragma unroll
    for (int i = 0; i < 4; i++) {
        int r = r0 + ty + i * 8, c = c0 + tx;
        if (r < R && c < C) tile[ty + i * 8][tx] = (float)in[(long long)r * ldi + c];
    }
    __syncthreads();
    #pragma unroll
    for (int i = 0; i < 4; i++) {
        int c = c0 + ty + i * 8, r = r0 + tx;
        if (r < R && c < C)
            out[(long long)c * ldo + r] = __float2half_rn(tile[tx][ty + i * 8]);
    }
}

// ---------------- layernorm: fp32 in, fp16 out ----------------
__device__ __forceinline__ float brsum(float v, float* sh) {
    int t = threadIdx.x;
    sh[t] = v; __syncthreads();
    #pragma unroll
    for (int s = 128; s > 0; s >>= 1) { if (t < s) sh[t] += sh[t + s]; __syncthreads(); }
    float r = sh[0]; __syncthreads();
    return r;
}

__global__ void __launch_bounds__(256) ln_kernel(
    const float* __restrict__ x, __half* __restrict__ y,
    const float* __restrict__ g, const float* __restrict__ b,
    float* __restrict__ cwgt, const float* __restrict__ alpha_ptr)
{
    long long base = (long long)blockIdx.x * DD;
    int t = threadIdx.x;
    __shared__ float sh[256];
    float xv[4];
    float s = 0.f;
    #pragma unroll
    for (int i = 0; i < 4; i++) { xv[i] = x[base + t + i * 256]; s += xv[i]; }
    s = brsum(s, sh);
    float mu = s * (1.0f / DD);
    float vs = 0.f;
    #pragma unroll
    for (int i = 0; i < 4; i++) { float d = xv[i] - mu; vs += d * d; }
    vs = brsum(vs, sh);
    float inv = rsqrtf(vs * (1.0f / DD) + 1e-5f);
    float ss = 0.f;
    #pragma unroll
    for (int i = 0; i < 4; i++) {
        int c = t + i * 256;
        float yv = (xv[i] - mu) * inv * g[c] + b[c];
        y[base + c] = __float2half_rn(yv);
        ss += yv * yv;
    }
    if (cwgt) {
        ss = brsum(ss, sh);
        if (t == 0) cwgt[blockIdx.x] = expf(-alpha_ptr[0] * sqrtf(ss));
    }
}

// ---------------- Qg = Q*cos(ph[h]) - V*sin(ph[h]) (fp16, packed QKV) ----------------
__global__ void __launch_bounds__(256) qg_kernel(
    const __half* __restrict__ QKV, const float* __restrict__ phase,
    __half* __restrict__ Qg)
{
    int i = blockIdx.x * 256 + threadIdx.x;
    if (i >= NELT) return;
    int tok = i >> 10, col = i & (DD - 1);
    int h = col >> 6;
    float p = phase[h];
    long long base = (long long)tok * (3 * DD) + col;
    Qg[i] = __float2half_rn(__half2float(QKV[base]) * cosf(p)
                            - __half2float(QKV[base + 2 * DD]) * sinf(p));
}

// ---------------- host helpers ----------------
template<int BM, int BN, int MT, bool ATTN, int MODE>
static void run_gemm(const __half* A, const __half* B, void* C, float* Aout, float* rowsum,
    int M, int N, int K, int lda, int ldb, int ldc,
    int batch, int batchH,
    long long sAb, long long sAh, long long sBb, long long sBh,
    long long sCb, long long sCh,
    float scale, const float* bias, const float* res,
    const __half* h2p, const float* cwgt, const float* betap)
{
    int smem = 3 * (BM + BN) * SPAD * 4;
    cudaFuncSetAttribute(tc_gemm<BM, BN, MT, ATTN, MODE>,
                         cudaFuncAttributeMaxDynamicSharedMemorySize, smem);
    dim3 grid(N / BN, M / BM, batch);
    tc_gemm<BM, BN, MT, ATTN, MODE><<<grid, 256, smem>>>(
        A, B, C, Aout, rowsum, M, K, lda, ldb, ldc,
        batchH, sAb, sAh, sBb, sBh, sCb, sCh,
        scale, bias, res, h2p, cwgt, betap);
}

template<typename TI>
static void launch_tr(const TI* in, __half* out, int R, int C, int ldi, int ldo,
    int batch, int batchH, long long sIb, long long sIh, long long sOb, long long sOh)
{
    dim3 grid((C + 31) / 32, (R + 31) / 32, batch);
    transpose_kernel<TI><<<grid, 256>>>(in, out, R, C, ldi, ldo,
                                        batchH, sIb, sIh, sOb, sOh);
}

extern "C" void kernel_launch(void* const* d_in, const int* in_sizes, int n_in,
                              void* d_out, int out_size)
{
    const float* x     = (const float*)d_in[0];
    const float* wq    = (const float*)d_in[1];
    const float* wk    = (const float*)d_in[2];
    const float* wv    = (const float*)d_in[3];
    const float* wo    = (const float*)d_in[4];
    const float* phase = (const float*)d_in[5];
    const float* cw1   = (const float*)d_in[6];
    const float* cb1   = (const float*)d_in[7];
    const float* cw2   = (const float*)d_in[8];
    const float* cb2   = (const float*)d_in[9];
    const float* alpha = (const float*)d_in[10];
    const float* beta  = (const float*)d_in[11];
    const float* fw1   = (const float*)d_in[12];
    const float* fb1   = (const float*)d_in[13];
    const float* fw2   = (const float*)d_in[14];
    const float* fb2   = (const float*)d_in[15];
    const float* ln1g  = (const float*)d_in[16];
    const float* ln1b  = (const float*)d_in[17];
    const float* ln2g  = (const float*)d_in[18];
    const float* ln2b  = (const float*)d_in[19];
    const float* ln3g  = (const float*)d_in[20];
    const float* ln3b  = (const float*)d_in[21];

    static __half *p_h=0,*p_QKV=0,*p_Qg=0,*p_VT=0,*p_ctx=0,*p_h2=0,*p_t1=0,*p_ff1=0,
                  *p_wqkvT=0,*p_woT=0,*p_cw1T=0,*p_cw2T=0,*p_fw1T=0,*p_fw2T=0,*p_e=0;
    static float *p_x1=0,*p_x2=0,*p_cwgt=0,*p_rowsum=0,*p_attn_fb=0;
    if (!p_h) {
        cudaGetSymbolAddress((void**)&p_h,    g_h);
        cudaGetSymbolAddress((void**)&p_QKV,  g_QKV);
        cudaGetSymbolAddress((void**)&p_Qg,   g_Qg);
        cudaGetSymbolAddress((void**)&p_VT,   g_VT);
        cudaGetSymbolAddress((void**)&p_ctx,  g_ctx);
        cudaGetSymbolAddress((void**)&p_x1,   g_x1);
        cudaGetSymbolAddress((void**)&p_h2,   g_h2);
        cudaGetSymbolAddress((void**)&p_x2,   g_x2);
        cudaGetSymbolAddress((void**)&p_t1,   g_t1);
        cudaGetSymbolAddress((void**)&p_ff1,  g_ff1);
        cudaGetSymbolAddress((void**)&p_cwgt, g_cwgt);
        cudaGetSymbolAddress((void**)&p_rowsum, g_rowsum);
        cudaGetSymbolAddress((void**)&p_e,    g_e);
        cudaGetSymbolAddress((void**)&p_attn_fb, g_attn_fb);
        cudaGetSymbolAddress((void**)&p_wqkvT, g_wqkvT);
        cudaGetSymbolAddress((void**)&p_woT,  g_woT);
        cudaGetSymbolAddress((void**)&p_cw1T, g_cw1T);
        cudaGetSymbolAddress((void**)&p_cw2T, g_cw2T);
        cudaGetSymbolAddress((void**)&p_fw1T, g_fw1T);
        cudaGetSymbolAddress((void**)&p_fw2T, g_fw2T);
    }

    float* out_x = (float*)d_out;
    long long need = (long long)NELT + ASZ;
    float* attn = ((long long)out_size >= need) ? (out_x + NELT) : p_attn_fb;

    // weight transposes (fp32 -> fp16, W[K,N] -> WT[N,K]); qkv packed [3072,1024]
    launch_tr(wq,  p_wqkvT,             DD,   DD,  DD,   DD,   1, 1, 0,0,0,0);
    launch_tr(wk,  p_wqkvT + DD*DD,     DD,   DD,  DD,   DD,   1, 1, 0,0,0,0);
    launch_tr(wv,  p_wqkvT + 2*DD*DD,   DD,   DD,  DD,   DD,   1, 1, 0,0,0,0);
    launch_tr(wo,  p_woT,  DD,   DD,  DD,   DD,   1, 1, 0,0,0,0);
    launch_tr(cw1, p_cw1T, DD,   2*DD, 2*DD, DD,  1, 1, 0,0,0,0);
    launch_tr(cw2, p_cw2T, 2*DD, DD,  DD,   2*DD, 1, 1, 0,0,0,0);
    launch_tr(fw1, p_fw1T, DD,   FFN, FFN,  DD,   1, 1, 0,0,0,0);
    launch_tr(fw2, p_fw2T, FFN,  DD,  DD,   FFN,  1, 1, 0,0,0,0);

    // 0) zero row sums
    zero_kernel<<<(NROWS + 255) / 256, 256>>>(p_rowsum, NROWS);

    // 1) h = LN1(x)  (fp16)
    ln_kernel<<<NTOK, 256>>>(x, p_h, ln1g, ln1b, nullptr, nullptr);

    // 2) QKV = h @ [wq|wk|wv]  (one GEMM, N=3072, fp16 out)
    run_gemm<256,128,4,false,1>(p_h, p_wqkvT, p_QKV, 0, 0, NTOK, 3*DD, DD,
                                DD, DD, 3*DD,
                                1,1, 0,0,0,0,0,0, 1.f, 0,0,0,0,0);

    // 3) Qg (fp16)
    qg_kernel<<<(NELT + 255) / 256, 256>>>(p_QKV, phase, p_Qg);

    // 3b) VT[b,h,d,s] = V[b,s,h,d]  (fp16 -> fp16)
    launch_tr(p_QKV + 2*DD, p_VT, SS, DKK, 3*DD, SS,
              BB * HH, HH,
              (long long)SS * 3*DD, DKK,
              (long long)HH * DKK * SS, (long long)DKK * SS);

    // 4) e = h(exp(Qg @ K^T / 8)) + row sums of rounded e
    run_gemm<256,128,4,false,5>(p_Qg, p_QKV + DD, p_e, 0, p_rowsum,
                                SS, SS, DKK, DD, 3*DD, SS,
                                BB * HH, HH,
                                (long long)SS * DD, DKK,
                                (long long)SS * 3*DD, DKK,
                                (long long)HH * SS * SS, (long long)SS * SS,
                                0.125f, 0,0,0,0,0);

    // 5+6) ctx = (e/rowsum) @ V  — streams normalized fp32 attn_weights
    run_gemm<128,64,1,true,6>(p_e, p_VT, p_ctx, attn, p_rowsum,
                              SS, DKK, SS, SS, SS, DD,
                              BB * HH, HH,
                              (long long)HH * SS * SS, (long long)SS * SS,
                              (long long)HH * DKK * SS, (long long)DKK * SS,
                              (long long)SS * DD, DKK,
                              1.f, 0,0,0,0,0);

    // 7) x1 = x + ctx @ wo  (fp32 out)
    run_gemm<256,128,4,false,3>(p_ctx, p_woT, p_x1, 0, 0, NTOK, DD, DD, DD, DD, DD,
                                1,1, 0,0,0,0,0,0, 1.f, 0, x, 0,0,0);

    // 8) h2 = LN2(x1) + cwgt  (fp16)
    ln_kernel<<<NTOK, 256>>>(p_x1, p_h2, ln2g, ln2b, p_cwgt, alpha);

    // 9) t1 = gelu(h2 @ cw1 + cb1)  (fp16 out)
    run_gemm<256,128,4,false,2>(p_h2, p_cw1T, p_t1, 0, 0, NTOK, 2*DD, DD, DD, DD, 2*DD,
                                1,1, 0,0,0,0,0,0, 1.f, cb1, 0,0,0,0);

    // 10) x2 = x1 + beta*h2 + cwgt*(t1 @ cw2 + cb2)  (fp32 out)
    run_gemm<256,128,4,false,4>(p_t1, p_cw2T, p_x2, 0, 0, NTOK, DD, 2*DD, 2*DD, 2*DD, DD,
                                1,1, 0,0,0,0,0,0, 1.f, cb2, p_x1, p_h2, p_cwgt, beta);

    // 11) h3 = LN3(x2)  (fp16)
    ln_kernel<<<NTOK, 256>>>(p_x2, p_h, ln3g, ln3b, nullptr, nullptr);

    // 12) ff1 = gelu(h3 @ fw1 + fb1)  (fp16 out)
    run_gemm<256,128,4,false,2>(p_h, p_fw1T, p_ff1, 0, 0, NTOK, FFN, DD, DD, DD, FFN,
                                1,1, 0,0,0,0,0,0, 1.f, fb1, 0,0,0,0);

    // 13) out = x2 + ff1 @ fw2 + fb2  (fp32 out)
    run_gemm<256,128,4,false,3>(p_ff1, p_fw2T, out_x, 0, 0, NTOK, DD, FFN, FFN, FFN, DD,
                                1,1, 0,0,0,0,0,0, 1.f, fb2, p_x2, 0,0,0);
}